// round 15
// baseline (speedup 1.0000x reference)
#include <cuda_runtime.h>
#include <cstdint>

#define NN 50000
#define NE 500000
#define D 128
#define NL 4
#define NG 64
#define FIXEDDIM 10000
#define BNEPS 1e-5f

// ---------------- scratch (device globals) ----------------------------------
__device__ float g_h[NN * D];
__device__ float g_z1[NN * D];
__device__ float g_z2[NN * D];
__device__ int g_deg[NN];
__device__ int g_rowptr[NN + 1];
__device__ int g_cursor[NN];
__device__ int g_col[NE];
__device__ int g_starts[NG + 1];
__device__ double g_bsum8[8 * D];
__device__ double g_bsq8[8 * D];
__device__ uint4 g_bw4[8 * 4352];   // packed bf16 hi/lo W, [gemm][n][k2][hi,lo], 136 words/row

// ---------------- helpers ----------------------------------------------------
__device__ __forceinline__ void pack_hilo(float v0, float v1, uint32_t& hp, uint32_t& lp) {
    asm("cvt.rn.bf16x2.f32 %0, %1, %2;" : "=r"(hp) : "f"(v1), "f"(v0));
    float h0 = __uint_as_float(hp << 16);
    float h1 = __uint_as_float(hp & 0xffff0000u);
    float r0 = v0 - h0, r1 = v1 - h1;
    asm("cvt.rn.bf16x2.f32 %0, %1, %2;" : "=r"(lp) : "f"(r1), "f"(r0));
}

__device__ __forceinline__ void bn_params(int slot, const float* __restrict__ g,
                                          const float* __restrict__ b, int c,
                                          float& sc, float& sh) {
    double m = g_bsum8[slot * D + c] / (double)NN;
    double var = g_bsq8[slot * D + c] / (double)NN - m * m;
    float s = g[c] * rsqrtf((float)var + BNEPS);
    sc = s;
    sh = b[c] - (float)m * s;
}

#define MMA16(cc, a, b) \
    asm volatile("mma.sync.aligned.m16n8k16.row.col.f32.bf16.bf16.f32 " \
                 "{%0,%1,%2,%3},{%4,%5,%6,%7},{%8,%9},{%0,%1,%2,%3};" \
                 : "+f"((cc)[0]), "+f"((cc)[1]), "+f"((cc)[2]), "+f"((cc)[3]) \
                 : "r"((a)[0]), "r"((a)[1]), "r"((a)[2]), "r"((a)[3]), \
                   "r"((b)[0]), "r"((b)[1]))

__device__ __forceinline__ float4 affrelu(float4 a, float4 s, float4 h) {
    a.x = fmaxf(a.x * s.x + h.x, 0.f);
    a.y = fmaxf(a.y * s.y + h.y, 0.f);
    a.z = fmaxf(a.z * s.z + h.z, 0.f);
    a.w = fmaxf(a.w * s.w + h.w, 0.f);
    return a;
}
__device__ __forceinline__ void acc4(float4& a, float4 t) {
    a.x += t.x; a.y += t.y; a.z += t.z; a.w += t.w;
}
// streaming load, L2-only (keeps B resident in L1)
__device__ __forceinline__ float4 ldcg4(const float4* p) {
    float4 v;
    asm volatile("ld.global.cg.v4.f32 {%0,%1,%2,%3}, [%4];"
                 : "=f"(v.x), "=f"(v.y), "=f"(v.z), "=f"(v.w) : "l"(p));
    return v;
}
__device__ __forceinline__ float2 ldcg2(const float2* p) {
    float2 v;
    asm volatile("ld.global.cg.v2.f32 {%0,%1}, [%2];" : "=f"(v.x), "=f"(v.y) : "l"(p));
    return v;
}

// ---------------- launch #1: zero + prepw ------------------------------------
__global__ void k_setup0(const float* __restrict__ w1, const float* __restrict__ w2) {
    int i = blockIdx.x * 256 + threadIdx.x;  // 0..65535
    if (i < NN) g_deg[i] = 0;
    if (i < 8 * D) { g_bsum8[i] = 0.0; g_bsq8[i] = 0.0; }
    int j = i >> 13, rem = i & 8191;
    int n = rem >> 6, k2 = rem & 63;
    int l = j >> 1;
    const float* W = (j & 1) ? w2 : w1;
    float v0 = W[l * D * D + (2 * k2) * D + n];
    float v1 = W[l * D * D + (2 * k2 + 1) * D + n];
    uint32_t hp, lp;
    pack_hilo(v0, v1, hp, lp);
    uint32_t* bw = (uint32_t*)g_bw4;
    bw[j * 17408 + n * 136 + k2 * 2] = hp;
    bw[j * 17408 + n * 136 + k2 * 2 + 1] = lp;
}

// ---------------- launch #2: degree count ------------------------------------
__global__ void k_deg(const int* __restrict__ dst) {
    int e = blockIdx.x * blockDim.x + threadIdx.x;
    if (e < NE) atomicAdd(&g_deg[dst[e]], 1);
}

// ---------------- launch #3: emit rowptr/cursor -------------------------------
__global__ void k_emit() {
    __shared__ int wsum[32];
    __shared__ int sred[32];
    int tid = threadIdx.x;
    int lane = tid & 31, wid = tid >> 5;
    int base = blockIdx.x * 1024;

    int pre = 0;
    for (int i = tid; i < base; i += 1024) pre += g_deg[i];
#pragma unroll
    for (int off = 16; off > 0; off >>= 1) pre += __shfl_down_sync(0xffffffffu, pre, off);
    if (lane == 0) sred[wid] = pre;
    __syncthreads();
    if (tid < 32) {
        int v = sred[tid];
#pragma unroll
        for (int off = 16; off > 0; off >>= 1) v += __shfl_down_sync(0xffffffffu, v, off);
        if (tid == 0) sred[0] = v;
    }

    int i = base + tid;
    int d = (i < NN) ? g_deg[i] : 0;
    int x = d;
#pragma unroll
    for (int off = 1; off < 32; off <<= 1) {
        int y = __shfl_up_sync(0xffffffffu, x, off);
        if (lane >= off) x += y;
    }
    if (lane == 31) wsum[wid] = x;
    __syncthreads();
    if (tid < 32) {
        int w = wsum[tid];
#pragma unroll
        for (int off = 1; off < 32; off <<= 1) {
            int y = __shfl_up_sync(0xffffffffu, w, off);
            if (tid >= off) w += y;
        }
        wsum[tid] = w;
    }
    __syncthreads();
    int poff = sred[0];
    if (i < NN) {
        int excl = x - d + (wid ? wsum[wid - 1] : 0) + poff;
        g_rowptr[i] = excl;
        g_cursor[i] = excl;
    }
    if (i == 0) g_rowptr[NN] = NE;
}

// ---------------- launch #4: fill + init + bounds -----------------------------
#define FILL_BLKS 1954
#define INIT_BLKS 6250
#define BND_BLKS 196
__global__ void k_setup1(const int* __restrict__ src, const int* __restrict__ dst,
                         const int* __restrict__ feat_id,
                         const float4* __restrict__ w, const float4* __restrict__ b,
                         const float4* __restrict__ demb, const int* __restrict__ batch) {
    int blk = blockIdx.x;
    if (blk < FILL_BLKS) {
        int e = blk * 256 + threadIdx.x;
        if (e < NE) {
            int pos = atomicAdd(&g_cursor[dst[e]], 1);
            g_col[pos] = src[e];
        }
    } else if (blk < FILL_BLKS + INIT_BLKS) {
        int i = (blk - FILL_BLKS) * 256 + threadIdx.x;
        int v = i >> 5, j = i & 31;
        if (v >= NN) return;
        int fid = feat_id[v] % FIXEDDIM;
        int dg = g_deg[v];
        if (dg > 1000) dg = 1000;
        float4 a = w[fid * 32 + j];
        float4 bb = b[j];
        float4 dd = demb[dg * 32 + j];
        float4 r;
        r.x = a.x + bb.x + dd.x;
        r.y = a.y + bb.y + dd.y;
        r.z = a.z + bb.z + dd.z;
        r.w = a.w + bb.w + dd.w;
        ((float4*)g_h)[v * 32 + j] = r;
    } else {
        int i = (blk - FILL_BLKS - INIT_BLKS) * 256 + threadIdx.x;
        if (i >= NN) return;
        if (i == 0) {
            g_starts[batch[0]] = 0;
            g_starts[NG] = NN;
        } else if (batch[i] != batch[i - 1]) {
            g_starts[batch[i]] = i;
        }
    }
}

// ---------------- persistent bf16x3 GEMM: B in L1, As in smem, 3 blocks/SM ----
// MODE 0: A = gather(g_h)            -> out g_z1
// MODE 1: A = gather(affrelu(g_z2))  -> out g_z1
// MODE 2: A = affrelu(g_z1)          -> out g_z2
// smem words: As[64][136]=8704 | ssum128 ssq128 ssc128 ssh128 -> 9216 words
#define SMW_SSUM 8704
#define SMW_SSQ 8832
#define SMW_SC 8960
#define SMW_SH 9088
#define GEMM_SMEM (9216 * 4)
#define NTILES ((NN + 63) / 64)  // 782
#define GEMM_GRID 444            // 3 blocks/SM x 148

template <int MODE>
__global__ __launch_bounds__(256, 3) void k_gemm(
    int wsel, const float* __restrict__ bias,
    const float* __restrict__ bng, const float* __restrict__ bnb,
    int inSlot, int outSlot) {
    float* __restrict__ out = (MODE == 2) ? g_z2 : g_z1;
    const uint32_t* __restrict__ Bw = (const uint32_t*)g_bw4 + wsel * 17408;

    extern __shared__ uint32_t S[];
    float* ssum = (float*)(S + SMW_SSUM);
    float* ssq = (float*)(S + SMW_SSQ);
    float* ssc = (float*)(S + SMW_SC);
    float* ssh = (float*)(S + SMW_SH);

    int tid = threadIdx.x, lane = tid & 31, wid = tid >> 5;
    int warp_m = wid >> 2, warp_n = wid & 3;
    int g = lane >> 2, tg = lane & 3;

    if (tid < 128) {
        ssum[tid] = 0.f;
        ssq[tid] = 0.f;
        if (MODE != 0) {
            float sc, sh;
            bn_params(inSlot, bng, bnb, tid, sc, sh);
            ssc[tid] = sc;
            ssh[tid] = sh;
        }
    }
    __syncthreads();

    float bb0[4], bb1[4];
#pragma unroll
    for (int u = 0; u < 4; u++) {
        int col = warp_n * 32 + u * 8 + tg * 2;
        bb0[u] = __ldg(&bias[col]);
        bb1[u] = __ldg(&bias[col + 1]);
    }
    float4 sc4, sh4;
    if (MODE == 1) {
        sc4 = ((float4*)ssc)[lane];
        sh4 = ((float4*)ssh)[lane];
    }

    float sl[8], ql[8];
#pragma unroll
    for (int j = 0; j < 8; j++) { sl[j] = 0.f; ql[j] = 0.f; }

    for (int tile = blockIdx.x; tile < NTILES; tile += GEMM_GRID) {
        int rowBase = tile * 64;

        if (MODE == 2) {
            float2 vb[16];
#pragma unroll
            for (int it = 0; it < 16; it++) {
                int i = it * 256 + tid;
                int row = i >> 6, kp = i & 63;
                int grow = rowBase + row;
                vb[it] = (grow < NN) ? ldcg2((const float2*)&g_z1[grow * D + kp * 2])
                                     : make_float2(0.f, 0.f);
            }
#pragma unroll
            for (int it = 0; it < 16; it++) {
                int i = it * 256 + tid;
                int row = i >> 6, kp = i & 63;
                float2 v = vb[it];
                v.x = fmaxf(v.x * ssc[kp * 2] + ssh[kp * 2], 0.f);
                v.y = fmaxf(v.y * ssc[kp * 2 + 1] + ssh[kp * 2 + 1], 0.f);
                uint32_t hp, lp;
                pack_hilo(v.x, v.y, hp, lp);
                *(uint2*)(S + row * 136 + kp * 2) = make_uint2(hp, lp);
            }
        } else {
            const float4* __restrict__ h4 = (MODE == 0) ? (const float4*)g_h
                                                        : (const float4*)g_z2;
#pragma unroll
            for (int rr = 0; rr < 8; rr++) {
                int row = wid * 8 + rr;
                int v = rowBase + row;
                float4 a0 = make_float4(0.f, 0.f, 0.f, 0.f);
                float4 a1 = a0, a2 = a0, a3 = a0;
                if (v < NN) {
                    a0 = ldcg4(&h4[v * 32 + lane]);
                    if (MODE == 1) a0 = affrelu(a0, sc4, sh4);
                    int beg = g_rowptr[v], end = g_rowptr[v + 1];
                    int j = beg;
                    for (; j + 7 < end; j += 8) {
                        int s0 = g_col[j],     s1 = g_col[j + 1];
                        int s2 = g_col[j + 2], s3 = g_col[j + 3];
                        int s4 = g_col[j + 4], s5 = g_col[j + 5];
                        int s6 = g_col[j + 6], s7 = g_col[j + 7];
                        float4 t0 = ldcg4(&h4[s0 * 32 + lane]);
                        float4 t1 = ldcg4(&h4[s1 * 32 + lane]);
                        float4 t2 = ldcg4(&h4[s2 * 32 + lane]);
                        float4 t3 = ldcg4(&h4[s3 * 32 + lane]);
                        float4 t4 = ldcg4(&h4[s4 * 32 + lane]);
                        float4 t5 = ldcg4(&h4[s5 * 32 + lane]);
                        float4 t6 = ldcg4(&h4[s6 * 32 + lane]);
                        float4 t7 = ldcg4(&h4[s7 * 32 + lane]);
                        if (MODE == 1) {
                            t0 = affrelu(t0, sc4, sh4); t1 = affrelu(t1, sc4, sh4);
                            t2 = affrelu(t2, sc4, sh4); t3 = affrelu(t3, sc4, sh4);
                            t4 = affrelu(t4, sc4, sh4); t5 = affrelu(t5, sc4, sh4);
                            t6 = affrelu(t6, sc4, sh4); t7 = affrelu(t7, sc4, sh4);
                        }
                        acc4(a0, t0); acc4(a1, t1); acc4(a2, t2); acc4(a3, t3);
                        acc4(a0, t4); acc4(a1, t5); acc4(a2, t6); acc4(a3, t7);
                    }
                    for (; j + 3 < end; j += 4) {
                        int s0 = g_col[j], s1 = g_col[j + 1];
                        int s2 = g_col[j + 2], s3 = g_col[j + 3];
                        float4 t0 = ldcg4(&h4[s0 * 32 + lane]);
                        float4 t1 = ldcg4(&h4[s1 * 32 + lane]);
                        float4 t2 = ldcg4(&h4[s2 * 32 + lane]);
                        float4 t3 = ldcg4(&h4[s3 * 32 + lane]);
                        if (MODE == 1) {
                            t0 = affrelu(t0, sc4, sh4); t1 = affrelu(t1, sc4, sh4);
                            t2 = affrelu(t2, sc4, sh4); t3 = affrelu(t3, sc4, sh4);
                        }
                        acc4(a0, t0); acc4(a1, t1); acc4(a2, t2); acc4(a3, t3);
                    }
                    for (; j < end; j++) {
                        float4 t = ldcg4(&h4[g_col[j] * 32 + lane]);
                        if (MODE == 1) t = affrelu(t, sc4, sh4);
                        acc4(a0, t);
                    }
                    acc4(a0, a1); acc4(a2, a3); acc4(a0, a2);
                }
                uint32_t h0, l0, h1, l1;
                pack_hilo(a0.x, a0.y, h0, l0);
                pack_hilo(a0.z, a0.w, h1, l1);
                *(uint4*)(S + row * 136 + lane * 4) = make_uint4(h0, l0, h1, l1);
            }
        }
        __syncthreads();

        float c[2][4][4];
#pragma unroll
        for (int t = 0; t < 2; t++)
#pragma unroll
            for (int u = 0; u < 4; u++)
#pragma unroll
                for (int j = 0; j < 4; j++) c[t][u][j] = 0.f;

#pragma unroll
        for (int ks = 0; ks < 8; ks++) {
            int kw = (ks * 8 + tg) * 2;
            uint32_t ah[2][4], al[2][4];
#pragma unroll
            for (int t = 0; t < 2; t++) {
                int r0 = warp_m * 32 + t * 16 + g;
                uint2 p0 = *(uint2*)(S + r0 * 136 + kw);
                uint2 p1 = *(uint2*)(S + (r0 + 8) * 136 + kw);
                uint2 p2 = *(uint2*)(S + r0 * 136 + kw + 8);
                uint2 p3 = *(uint2*)(S + (r0 + 8) * 136 + kw + 8);
                ah[t][0] = p0.x; al[t][0] = p0.y;
                ah[t][1] = p1.x; al[t][1] = p1.y;
                ah[t][2] = p2.x; al[t][2] = p2.y;
                ah[t][3] = p3.x; al[t][3] = p3.y;
            }
#pragma unroll
            for (int u = 0; u < 4; u++) {
                int n = warp_n * 32 + u * 8 + g;
                // B fragments from global via L1 (read-only, shared across blocks)
                uint2 q0 = __ldg((const uint2*)&Bw[n * 136 + kw]);
                uint2 q1 = __ldg((const uint2*)&Bw[n * 136 + kw + 8]);
                uint32_t bh[2] = {q0.x, q1.x};
                uint32_t bl[2] = {q0.y, q1.y};
                MMA16(c[0][u], ah[0], bh);
                MMA16(c[1][u], ah[1], bh);
                MMA16(c[0][u], al[0], bh);
                MMA16(c[1][u], al[1], bh);
                MMA16(c[0][u], ah[0], bl);
                MMA16(c[1][u], ah[1], bl);
            }
        }

#pragma unroll
        for (int u = 0; u < 4; u++) {
            int col = warp_n * 32 + u * 8 + tg * 2;
#pragma unroll
            for (int t = 0; t < 2; t++) {
                int row0 = rowBase + warp_m * 32 + t * 16 + g;
                float v0 = c[t][u][0] + bb0[u], v1 = c[t][u][1] + bb1[u];
                if (row0 < NN) {
                    *(float2*)&out[row0 * D + col] = make_float2(v0, v1);
                    sl[u * 2] += v0; ql[u * 2] += v0 * v0;
                    sl[u * 2 + 1] += v1; ql[u * 2 + 1] += v1 * v1;
                }
                int row1 = row0 + 8;
                float v2 = c[t][u][2] + bb0[u], v3 = c[t][u][3] + bb1[u];
                if (row1 < NN) {
                    *(float2*)&out[row1 * D + col] = make_float2(v2, v3);
                    sl[u * 2] += v2; ql[u * 2] += v2 * v2;
                    sl[u * 2 + 1] += v3; ql[u * 2 + 1] += v3 * v3;
                }
            }
        }
        __syncthreads();
    }

    // one-time BN stat reduction
#pragma unroll
    for (int j = 0; j < 8; j++) {
#pragma unroll
        for (int off = 4; off < 32; off <<= 1) {
            sl[j] += __shfl_xor_sync(0xffffffffu, sl[j], off);
            ql[j] += __shfl_xor_sync(0xffffffffu, ql[j], off);
        }
    }
    if (g == 0) {
#pragma unroll
        for (int u = 0; u < 4; u++) {
            int col = warp_n * 32 + u * 8 + tg * 2;
            atomicAdd(&ssum[col], sl[u * 2]);
            atomicAdd(&ssq[col], ql[u * 2]);
            atomicAdd(&ssum[col + 1], sl[u * 2 + 1]);
            atomicAdd(&ssq[col + 1], ql[u * 2 + 1]);
        }
    }
    __syncthreads();
    if (tid < 128) {
        atomicAdd(&g_bsum8[outSlot * D + tid], (double)ssum[tid]);
        atomicAdd(&g_bsq8[outSlot * D + tid], (double)ssq[tid]);
    }
}

// ---------------- pooling (fused final BN-affine+relu) -----------------------
__global__ void k_poolact(int slot, const float* __restrict__ bng,
                          const float* __restrict__ bnb,
                          float* __restrict__ out_h, float* __restrict__ out_gf) {
    __shared__ float ssc[128], ssh[128], sh[256];
    if (threadIdx.x < 128) {
        float sc, s2;
        bn_params(slot, bng, bnb, threadIdx.x, sc, s2);
        ssc[threadIdx.x] = sc;
        ssh[threadIdx.x] = s2;
    }
    __syncthreads();
    int g = blockIdx.x;
    int s = g_starts[g], e = g_starts[g + 1];
    int col = threadIdx.x & 127, half = threadIdx.x >> 7;
    float sc = ssc[col], sf = ssh[col];
    float acc = 0.f;
    for (int r = s + half; r < e; r += 2) {
        float v = fmaxf(g_z2[r * D + col] * sc + sf, 0.f);
        out_h[r * D + col] = v;
        acc += v;
    }
    sh[threadIdx.x] = acc;
    __syncthreads();
    if (half == 0) {
        float tot = sh[threadIdx.x] + sh[threadIdx.x + 128];
        int cnt = e - s;
        if (cnt < 1) cnt = 1;
        out_gf[g * D + col] = tot / (float)cnt;
    }
}

// ---------------- launch -----------------------------------------------------
extern "C" void kernel_launch(void* const* d_in, const int* in_sizes, int n_in,
                              void* d_out, int out_size) {
    const int* feat_id = (const int*)d_in[0];
    const int* ei      = (const int*)d_in[1];
    const int* batch   = (const int*)d_in[2];
    const float* vpw   = (const float*)d_in[3];
    const float* vpb   = (const float*)d_in[4];
    const float* demb  = (const float*)d_in[5];
    const float* w1    = (const float*)d_in[6];
    const float* b1    = (const float*)d_in[7];
    const float* g1    = (const float*)d_in[8];
    const float* bb1   = (const float*)d_in[9];
    const float* w2    = (const float*)d_in[10];
    const float* b2    = (const float*)d_in[11];
    const float* g2    = (const float*)d_in[12];
    const float* bb2   = (const float*)d_in[13];

    float* out    = (float*)d_out;
    float* out_gf = out;
    float* out_h  = out + NG * D;

    const int* src = ei;
    const int* dst = ei + NE;

    cudaFuncSetAttribute(k_gemm<0>, cudaFuncAttributeMaxDynamicSharedMemorySize, GEMM_SMEM);
    cudaFuncSetAttribute(k_gemm<1>, cudaFuncAttributeMaxDynamicSharedMemorySize, GEMM_SMEM);
    cudaFuncSetAttribute(k_gemm<2>, cudaFuncAttributeMaxDynamicSharedMemorySize, GEMM_SMEM);

    k_setup0<<<256, 256>>>(w1, w2);
    k_deg<<<(NE + 255) / 256, 256>>>(dst);
    k_emit<<<49, 1024>>>();
    k_setup1<<<FILL_BLKS + INIT_BLKS + BND_BLKS, 256>>>(
        src, dst, feat_id, (const float4*)vpw, (const float4*)vpb,
        (const float4*)demb, batch);

    for (int l = 0; l < NL; l++) {
        if (l == 0)
            k_gemm<0><<<GEMM_GRID, 256, GEMM_SMEM>>>(
                0, b1, (const float*)0, (const float*)0, -1, 0);
        else
            k_gemm<1><<<GEMM_GRID, 256, GEMM_SMEM>>>(
                2 * l, b1 + l * D, g2 + (l - 1) * D, bb2 + (l - 1) * D,
                2 * (l - 1) + 1, 2 * l);
        k_gemm<2><<<GEMM_GRID, 256, GEMM_SMEM>>>(
            2 * l + 1, b2 + l * D, g1 + l * D, bb1 + l * D, 2 * l, 2 * l + 1);
    }

    k_poolact<<<NG, 256>>>(7, g2 + 3 * D, bb2 + 3 * D, out_h, out_gf);
}

// round 16
// speedup vs baseline: 1.1778x; 1.1778x over previous
#include <cuda_runtime.h>
#include <cstdint>

#define NN 50000
#define NE 500000
#define D 128
#define NL 4
#define NG 64
#define FIXEDDIM 10000
#define BNEPS 1e-5f

// ---------------- scratch (device globals) ----------------------------------
__device__ float g_h[NN * D];
__device__ float g_z1[NN * D];
__device__ float g_z2[NN * D];
__device__ int g_deg[NN];
__device__ int g_rowptr[NN + 1];
__device__ int g_cursor[NN];
__device__ int g_col[NE];
__device__ int g_starts[NG + 1];
__device__ double g_bsum8[8 * D];
__device__ double g_bsq8[8 * D];
__device__ uint4 g_bw4[8 * 4352];   // packed bf16 hi/lo W, [gemm][n][k2][hi,lo], 136 words/row

// ---------------- helpers ----------------------------------------------------
__device__ __forceinline__ void pack_hilo(float v0, float v1, uint32_t& hp, uint32_t& lp) {
    asm("cvt.rn.bf16x2.f32 %0, %1, %2;" : "=r"(hp) : "f"(v1), "f"(v0));
    float h0 = __uint_as_float(hp << 16);
    float h1 = __uint_as_float(hp & 0xffff0000u);
    float r0 = v0 - h0, r1 = v1 - h1;
    asm("cvt.rn.bf16x2.f32 %0, %1, %2;" : "=r"(lp) : "f"(r1), "f"(r0));
}

__device__ __forceinline__ void bn_params(int slot, const float* __restrict__ g,
                                          const float* __restrict__ b, int c,
                                          float& sc, float& sh) {
    double m = g_bsum8[slot * D + c] / (double)NN;
    double var = g_bsq8[slot * D + c] / (double)NN - m * m;
    float s = g[c] * rsqrtf((float)var + BNEPS);
    sc = s;
    sh = b[c] - (float)m * s;
}

#define MMA16(cc, a, b) \
    asm volatile("mma.sync.aligned.m16n8k16.row.col.f32.bf16.bf16.f32 " \
                 "{%0,%1,%2,%3},{%4,%5,%6,%7},{%8,%9},{%0,%1,%2,%3};" \
                 : "+f"((cc)[0]), "+f"((cc)[1]), "+f"((cc)[2]), "+f"((cc)[3]) \
                 : "r"((a)[0]), "r"((a)[1]), "r"((a)[2]), "r"((a)[3]), \
                   "r"((b)[0]), "r"((b)[1]))

__device__ __forceinline__ float4 affrelu(float4 a, float4 s, float4 h) {
    a.x = fmaxf(a.x * s.x + h.x, 0.f);
    a.y = fmaxf(a.y * s.y + h.y, 0.f);
    a.z = fmaxf(a.z * s.z + h.z, 0.f);
    a.w = fmaxf(a.w * s.w + h.w, 0.f);
    return a;
}
__device__ __forceinline__ void acc4(float4& a, float4 t) {
    a.x += t.x; a.y += t.y; a.z += t.z; a.w += t.w;
}
__device__ __forceinline__ void pf_l2(const void* p) {
    asm volatile("prefetch.global.L2 [%0];" :: "l"(p));
}

// ---------------- launch #1: zero + prepw ------------------------------------
__global__ void k_setup0(const float* __restrict__ w1, const float* __restrict__ w2) {
    int i = blockIdx.x * 256 + threadIdx.x;  // 0..65535
    if (i < NN) g_deg[i] = 0;
    if (i < 8 * D) { g_bsum8[i] = 0.0; g_bsq8[i] = 0.0; }
    int j = i >> 13, rem = i & 8191;
    int n = rem >> 6, k2 = rem & 63;
    int l = j >> 1;
    const float* W = (j & 1) ? w2 : w1;
    float v0 = W[l * D * D + (2 * k2) * D + n];
    float v1 = W[l * D * D + (2 * k2 + 1) * D + n];
    uint32_t hp, lp;
    pack_hilo(v0, v1, hp, lp);
    uint32_t* bw = (uint32_t*)g_bw4;
    bw[j * 17408 + n * 136 + k2 * 2] = hp;
    bw[j * 17408 + n * 136 + k2 * 2 + 1] = lp;
}

// ---------------- launch #2: degree count ------------------------------------
__global__ void k_deg(const int* __restrict__ dst) {
    int e = blockIdx.x * blockDim.x + threadIdx.x;
    if (e < NE) atomicAdd(&g_deg[dst[e]], 1);
}

// ---------------- launch #3: emit rowptr/cursor -------------------------------
__global__ void k_emit() {
    __shared__ int wsum[32];
    __shared__ int sred[32];
    int tid = threadIdx.x;
    int lane = tid & 31, wid = tid >> 5;
    int base = blockIdx.x * 1024;

    int pre = 0;
    for (int i = tid; i < base; i += 1024) pre += g_deg[i];
#pragma unroll
    for (int off = 16; off > 0; off >>= 1) pre += __shfl_down_sync(0xffffffffu, pre, off);
    if (lane == 0) sred[wid] = pre;
    __syncthreads();
    if (tid < 32) {
        int v = sred[tid];
#pragma unroll
        for (int off = 16; off > 0; off >>= 1) v += __shfl_down_sync(0xffffffffu, v, off);
        if (tid == 0) sred[0] = v;
    }

    int i = base + tid;
    int d = (i < NN) ? g_deg[i] : 0;
    int x = d;
#pragma unroll
    for (int off = 1; off < 32; off <<= 1) {
        int y = __shfl_up_sync(0xffffffffu, x, off);
        if (lane >= off) x += y;
    }
    if (lane == 31) wsum[wid] = x;
    __syncthreads();
    if (tid < 32) {
        int w = wsum[tid];
#pragma unroll
        for (int off = 1; off < 32; off <<= 1) {
            int y = __shfl_up_sync(0xffffffffu, w, off);
            if (tid >= off) w += y;
        }
        wsum[tid] = w;
    }
    __syncthreads();
    int poff = sred[0];
    if (i < NN) {
        int excl = x - d + (wid ? wsum[wid - 1] : 0) + poff;
        g_rowptr[i] = excl;
        g_cursor[i] = excl;
    }
    if (i == 0) g_rowptr[NN] = NE;
}

// ---------------- launch #4: fill + init + bounds -----------------------------
#define FILL_BLKS 1954
#define INIT_BLKS 6250
#define BND_BLKS 196
__global__ void k_setup1(const int* __restrict__ src, const int* __restrict__ dst,
                         const int* __restrict__ feat_id,
                         const float4* __restrict__ w, const float4* __restrict__ b,
                         const float4* __restrict__ demb, const int* __restrict__ batch) {
    int blk = blockIdx.x;
    if (blk < FILL_BLKS) {
        int e = blk * 256 + threadIdx.x;
        if (e < NE) {
            int pos = atomicAdd(&g_cursor[dst[e]], 1);
            g_col[pos] = src[e];
        }
    } else if (blk < FILL_BLKS + INIT_BLKS) {
        int i = (blk - FILL_BLKS) * 256 + threadIdx.x;
        int v = i >> 5, j = i & 31;
        if (v >= NN) return;
        int fid = feat_id[v] % FIXEDDIM;
        int dg = g_deg[v];
        if (dg > 1000) dg = 1000;
        float4 a = w[fid * 32 + j];
        float4 bb = b[j];
        float4 dd = demb[dg * 32 + j];
        float4 r;
        r.x = a.x + bb.x + dd.x;
        r.y = a.y + bb.y + dd.y;
        r.z = a.z + bb.z + dd.z;
        r.w = a.w + bb.w + dd.w;
        ((float4*)g_h)[v * 32 + j] = r;
    } else {
        int i = (blk - FILL_BLKS - INIT_BLKS) * 256 + threadIdx.x;
        if (i >= NN) return;
        if (i == 0) {
            g_starts[batch[0]] = 0;
            g_starts[NG] = NN;
        } else if (batch[i] != batch[i - 1]) {
            g_starts[batch[i]] = i;
        }
    }
}

// ---------------- persistent bf16x3 GEMM, fused staging ----------------------
// MODE 0: A = gather(g_h)            -> out g_z1
// MODE 1: A = gather(affrelu(g_z2))  -> out g_z1
// MODE 2: A = affrelu(g_z1)          -> out g_z2
// smem words: As 8704 | Bs 17408 | ssum/ssq/ssc/ssh 512 | IDX 2048 (8 warps x 256)
#define SMW_BS 8704
#define SMW_SSUM 26112
#define SMW_SSQ 26240
#define SMW_SC 26368
#define SMW_SH 26496
#define SMW_IDX 26624
#define GEMM_SMEM (28672 * 4)
#define NTILES ((NN + 63) / 64)  // 782
#define GEMM_GRID 296

template <int MODE>
__global__ __launch_bounds__(256, 2) void k_gemm(
    int wsel, const float* __restrict__ bias,
    const float* __restrict__ bng, const float* __restrict__ bnb,
    int inSlot, int outSlot) {
    float* __restrict__ out = (MODE == 2) ? g_z2 : g_z1;
    const uint32_t* __restrict__ Bw = (const uint32_t*)g_bw4 + wsel * 17408;

    extern __shared__ uint32_t S[];
    float* ssum = (float*)(S + SMW_SSUM);
    float* ssq = (float*)(S + SMW_SSQ);
    float* ssc = (float*)(S + SMW_SC);
    float* ssh = (float*)(S + SMW_SH);

    int tid = threadIdx.x, lane = tid & 31, wid = tid >> 5;
    int warp_m = wid >> 2, warp_n = wid & 3;
    int g = lane >> 2, tg = lane & 3;

    if (tid < 128) {
        ssum[tid] = 0.f;
        ssq[tid] = 0.f;
        if (MODE != 0) {
            float sc, sh;
            bn_params(inSlot, bng, bnb, tid, sc, sh);
            ssc[tid] = sc;
            ssh[tid] = sh;
        }
    }
    // B: load once per block
    {
        const uint4* srcp = (const uint4*)Bw;
        uint4* dst = (uint4*)(S + SMW_BS);
#pragma unroll
        for (int i = 0; i < 17; i++) dst[tid + i * 256] = srcp[tid + i * 256];
    }
    __syncthreads();

    float bb0[4], bb1[4];
#pragma unroll
    for (int u = 0; u < 4; u++) {
        int col = warp_n * 32 + u * 8 + tg * 2;
        bb0[u] = __ldg(&bias[col]);
        bb1[u] = __ldg(&bias[col + 1]);
    }
    float4 sc4, sh4;
    if (MODE == 1) {
        sc4 = ((float4*)ssc)[lane];
        sh4 = ((float4*)ssh)[lane];
    }

    float sl[8], ql[8];
#pragma unroll
    for (int j = 0; j < 8; j++) { sl[j] = 0.f; ql[j] = 0.f; }

    for (int tile = blockIdx.x; tile < NTILES; tile += GEMM_GRID) {
        int rowBase = tile * 64;

        if (MODE == 2) {
            // two-phase dense staging: batch all 16 loads (MLP=16), then pack
            float2 vb[16];
#pragma unroll
            for (int it = 0; it < 16; it++) {
                int i = it * 256 + tid;
                int row = i >> 6, kp = i & 63;
                int grow = rowBase + row;
                vb[it] = (grow < NN) ? *(const float2*)&g_z1[grow * D + kp * 2]
                                     : make_float2(0.f, 0.f);
            }
#pragma unroll
            for (int it = 0; it < 16; it++) {
                int i = it * 256 + tid;
                int row = i >> 6, kp = i & 63;
                float2 v = vb[it];
                v.x = fmaxf(v.x * ssc[kp * 2] + ssh[kp * 2], 0.f);
                v.y = fmaxf(v.y * ssc[kp * 2 + 1] + ssh[kp * 2 + 1], 0.f);
                uint32_t hp, lp;
                pack_hilo(v.x, v.y, hp, lp);
                *(uint2*)(S + row * 136 + kp * 2) = make_uint2(hp, lp);
            }
        } else {
            const float4* __restrict__ h4 = (MODE == 0) ? (const float4*)g_h
                                                        : (const float4*)g_z2;
            int* IDX = (int*)(S + SMW_IDX) + wid * 256;
            int v0 = rowBase + wid * 8;
            // rowptr[v0 .. v0+8] via lanes 0..8 + shfl
            int rpi = v0 + (lane < 8 ? lane : 8);
            if (rpi > NN) rpi = NN;
            int rpl = g_rowptr[rpi];
            int base = __shfl_sync(0xffffffffu, rpl, 0);
            int cnt = __shfl_sync(0xffffffffu, rpl, 8) - base;
            // coalesced index staging (up to 256 per warp)
#pragma unroll
            for (int k = 0; k < 8; k++) {
                int p = k * 32 + lane;
                if (p < cnt) IDX[p] = g_col[base + p];
            }
            __syncwarp();
#pragma unroll
            for (int rr = 0; rr < 8; rr++) {
                int row = wid * 8 + rr;
                int v = rowBase + row;
                float4 a0 = make_float4(0.f, 0.f, 0.f, 0.f);
                float4 a1 = a0, a2 = a0, a3 = a0;
                if (v < NN) {
                    a0 = h4[v * 32 + lane];
                    if (MODE == 1) a0 = affrelu(a0, sc4, sh4);
                    int beg = __shfl_sync(0xffffffffu, rpl, rr) - base;
                    int end = __shfl_sync(0xffffffffu, rpl, rr + 1) - base;
                    int j = beg;
                    for (; j + 7 < end; j += 8) {
                        int s0, s1, s2, s3, s4, s5, s6, s7;
                        if (j + 7 < 256) {
                            s0 = IDX[j];     s1 = IDX[j + 1];
                            s2 = IDX[j + 2]; s3 = IDX[j + 3];
                            s4 = IDX[j + 4]; s5 = IDX[j + 5];
                            s6 = IDX[j + 6]; s7 = IDX[j + 7];
                        } else {
                            s0 = g_col[base + j];     s1 = g_col[base + j + 1];
                            s2 = g_col[base + j + 2]; s3 = g_col[base + j + 3];
                            s4 = g_col[base + j + 4]; s5 = g_col[base + j + 5];
                            s6 = g_col[base + j + 6]; s7 = g_col[base + j + 7];
                        }
                        float4 t0 = h4[s0 * 32 + lane];
                        float4 t1 = h4[s1 * 32 + lane];
                        float4 t2 = h4[s2 * 32 + lane];
                        float4 t3 = h4[s3 * 32 + lane];
                        float4 t4 = h4[s4 * 32 + lane];
                        float4 t5 = h4[s5 * 32 + lane];
                        float4 t6 = h4[s6 * 32 + lane];
                        float4 t7 = h4[s7 * 32 + lane];
                        if (MODE == 1) {
                            t0 = affrelu(t0, sc4, sh4); t1 = affrelu(t1, sc4, sh4);
                            t2 = affrelu(t2, sc4, sh4); t3 = affrelu(t3, sc4, sh4);
                            t4 = affrelu(t4, sc4, sh4); t5 = affrelu(t5, sc4, sh4);
                            t6 = affrelu(t6, sc4, sh4); t7 = affrelu(t7, sc4, sh4);
                        }
                        acc4(a0, t0); acc4(a1, t1); acc4(a2, t2); acc4(a3, t3);
                        acc4(a0, t4); acc4(a1, t5); acc4(a2, t6); acc4(a3, t7);
                    }
                    for (; j + 3 < end; j += 4) {
                        int s0, s1, s2, s3;
                        if (j + 3 < 256) {
                            s0 = IDX[j];     s1 = IDX[j + 1];
                            s2 = IDX[j + 2]; s3 = IDX[j + 3];
                        } else {
                            s0 = g_col[base + j];     s1 = g_col[base + j + 1];
                            s2 = g_col[base + j + 2]; s3 = g_col[base + j + 3];
                        }
                        float4 t0 = h4[s0 * 32 + lane];
                        float4 t1 = h4[s1 * 32 + lane];
                        float4 t2 = h4[s2 * 32 + lane];
                        float4 t3 = h4[s3 * 32 + lane];
                        if (MODE == 1) {
                            t0 = affrelu(t0, sc4, sh4); t1 = affrelu(t1, sc4, sh4);
                            t2 = affrelu(t2, sc4, sh4); t3 = affrelu(t3, sc4, sh4);
                        }
                        acc4(a0, t0); acc4(a1, t1); acc4(a2, t2); acc4(a3, t3);
                    }
                    for (; j < end; j++) {
                        int s = (j < 256) ? IDX[j] : g_col[base + j];
                        float4 t = h4[s * 32 + lane];
                        if (MODE == 1) t = affrelu(t, sc4, sh4);
                        acc4(a0, t);
                    }
                    acc4(a0, a1); acc4(a2, a3); acc4(a0, a2);
                }
                uint32_t h0, l0, h1, l1;
                pack_hilo(a0.x, a0.y, h0, l0);
                pack_hilo(a0.z, a0.w, h1, l1);
                *(uint4*)(S + row * 136 + lane * 4) = make_uint4(h0, l0, h1, l1);
            }
        }
        __syncthreads();

        float c[2][4][4];
#pragma unroll
        for (int t = 0; t < 2; t++)
#pragma unroll
            for (int u = 0; u < 4; u++)
#pragma unroll
                for (int j = 0; j < 4; j++) c[t][u][j] = 0.f;

#pragma unroll
        for (int ks = 0; ks < 8; ks++) {
            int kw = (ks * 8 + tg) * 2;
            uint32_t ah[2][4], al[2][4];
#pragma unroll
            for (int t = 0; t < 2; t++) {
                int r0 = warp_m * 32 + t * 16 + g;
                uint2 p0 = *(uint2*)(S + r0 * 136 + kw);
                uint2 p1 = *(uint2*)(S + (r0 + 8) * 136 + kw);
                uint2 p2 = *(uint2*)(S + r0 * 136 + kw + 8);
                uint2 p3 = *(uint2*)(S + (r0 + 8) * 136 + kw + 8);
                ah[t][0] = p0.x; al[t][0] = p0.y;
                ah[t][1] = p1.x; al[t][1] = p1.y;
                ah[t][2] = p2.x; al[t][2] = p2.y;
                ah[t][3] = p3.x; al[t][3] = p3.y;
            }
#pragma unroll
            for (int u = 0; u < 4; u++) {
                int n = warp_n * 32 + u * 8 + g;
                uint2 q0 = *(uint2*)(S + SMW_BS + n * 136 + kw);
                uint2 q1 = *(uint2*)(S + SMW_BS + n * 136 + kw + 8);
                uint32_t bh[2] = {q0.x, q1.x};
                uint32_t bl[2] = {q0.y, q1.y};
                MMA16(c[0][u], ah[0], bh);
                MMA16(c[1][u], ah[1], bh);
                MMA16(c[0][u], al[0], bh);
                MMA16(c[1][u], al[1], bh);
                MMA16(c[0][u], ah[0], bl);
                MMA16(c[1][u], ah[1], bl);
            }
        }

        // prefetch next tile's dense rows into L2 (MODE2 only; zero reg cost)
        if (MODE == 2) {
            int ntile = tile + GEMM_GRID;
            if (ntile < NTILES) {
                int nrowBase = ntile * 64;
#pragma unroll
                for (int it = 0; it < 16; it++) {
                    int i = it * 256 + tid;
                    int row = i >> 6, kp = i & 63;
                    int grow = nrowBase + row;
                    if (grow < NN) pf_l2(&g_z1[grow * D + kp * 2]);
                }
            }
        }

#pragma unroll
        for (int u = 0; u < 4; u++) {
            int col = warp_n * 32 + u * 8 + tg * 2;
#pragma unroll
            for (int t = 0; t < 2; t++) {
                int row0 = rowBase + warp_m * 32 + t * 16 + g;
                float v0 = c[t][u][0] + bb0[u], v1 = c[t][u][1] + bb1[u];
                if (row0 < NN) {
                    *(float2*)&out[row0 * D + col] = make_float2(v0, v1);
                    sl[u * 2] += v0; ql[u * 2] += v0 * v0;
                    sl[u * 2 + 1] += v1; ql[u * 2 + 1] += v1 * v1;
                }
                int row1 = row0 + 8;
                float v2 = c[t][u][2] + bb0[u], v3 = c[t][u][3] + bb1[u];
                if (row1 < NN) {
                    *(float2*)&out[row1 * D + col] = make_float2(v2, v3);
                    sl[u * 2] += v2; ql[u * 2] += v2 * v2;
                    sl[u * 2 + 1] += v3; ql[u * 2 + 1] += v3 * v3;
                }
            }
        }
        __syncthreads();
    }

    // one-time BN stat reduction
#pragma unroll
    for (int j = 0; j < 8; j++) {
#pragma unroll
        for (int off = 4; off < 32; off <<= 1) {
            sl[j] += __shfl_xor_sync(0xffffffffu, sl[j], off);
            ql[j] += __shfl_xor_sync(0xffffffffu, ql[j], off);
        }
    }
    if (g == 0) {
#pragma unroll
        for (int u = 0; u < 4; u++) {
            int col = warp_n * 32 + u * 8 + tg * 2;
            atomicAdd(&ssum[col], sl[u * 2]);
            atomicAdd(&ssq[col], ql[u * 2]);
            atomicAdd(&ssum[col + 1], sl[u * 2 + 1]);
            atomicAdd(&ssq[col + 1], ql[u * 2 + 1]);
        }
    }
    __syncthreads();
    if (tid < 128) {
        atomicAdd(&g_bsum8[outSlot * D + tid], (double)ssum[tid]);
        atomicAdd(&g_bsq8[outSlot * D + tid], (double)ssq[tid]);
    }
}

// ---------------- pooling (fused final BN-affine+relu) -----------------------
__global__ void k_poolact(int slot, const float* __restrict__ bng,
                          const float* __restrict__ bnb,
                          float* __restrict__ out_h, float* __restrict__ out_gf) {
    __shared__ float ssc[128], ssh[128], sh[256];
    if (threadIdx.x < 128) {
        float sc, s2;
        bn_params(slot, bng, bnb, threadIdx.x, sc, s2);
        ssc[threadIdx.x] = sc;
        ssh[threadIdx.x] = s2;
    }
    __syncthreads();
    int g = blockIdx.x;
    int s = g_starts[g], e = g_starts[g + 1];
    int col = threadIdx.x & 127, half = threadIdx.x >> 7;
    float sc = ssc[col], sf = ssh[col];
    float acc = 0.f;
    for (int r = s + half; r < e; r += 2) {
        float v = fmaxf(g_z2[r * D + col] * sc + sf, 0.f);
        out_h[r * D + col] = v;
        acc += v;
    }
    sh[threadIdx.x] = acc;
    __syncthreads();
    if (half == 0) {
        float tot = sh[threadIdx.x] + sh[threadIdx.x + 128];
        int cnt = e - s;
        if (cnt < 1) cnt = 1;
        out_gf[g * D + col] = tot / (float)cnt;
    }
}

// ---------------- launch -----------------------------------------------------
extern "C" void kernel_launch(void* const* d_in, const int* in_sizes, int n_in,
                              void* d_out, int out_size) {
    const int* feat_id = (const int*)d_in[0];
    const int* ei      = (const int*)d_in[1];
    const int* batch   = (const int*)d_in[2];
    const float* vpw   = (const float*)d_in[3];
    const float* vpb   = (const float*)d_in[4];
    const float* demb  = (const float*)d_in[5];
    const float* w1    = (const float*)d_in[6];
    const float* b1    = (const float*)d_in[7];
    const float* g1    = (const float*)d_in[8];
    const float* bb1   = (const float*)d_in[9];
    const float* w2    = (const float*)d_in[10];
    const float* b2    = (const float*)d_in[11];
    const float* g2    = (const float*)d_in[12];
    const float* bb2   = (const float*)d_in[13];

    float* out    = (float*)d_out;
    float* out_gf = out;
    float* out_h  = out + NG * D;

    const int* src = ei;
    const int* dst = ei + NE;

    cudaFuncSetAttribute(k_gemm<0>, cudaFuncAttributeMaxDynamicSharedMemorySize, GEMM_SMEM);
    cudaFuncSetAttribute(k_gemm<1>, cudaFuncAttributeMaxDynamicSharedMemorySize, GEMM_SMEM);
    cudaFuncSetAttribute(k_gemm<2>, cudaFuncAttributeMaxDynamicSharedMemorySize, GEMM_SMEM);

    k_setup0<<<256, 256>>>(w1, w2);
    k_deg<<<(NE + 255) / 256, 256>>>(dst);
    k_emit<<<49, 1024>>>();
    k_setup1<<<FILL_BLKS + INIT_BLKS + BND_BLKS, 256>>>(
        src, dst, feat_id, (const float4*)vpw, (const float4*)vpb,
        (const float4*)demb, batch);

    for (int l = 0; l < NL; l++) {
        if (l == 0)
            k_gemm<0><<<GEMM_GRID, 256, GEMM_SMEM>>>(
                0, b1, (const float*)0, (const float*)0, -1, 0);
        else
            k_gemm<1><<<GEMM_GRID, 256, GEMM_SMEM>>>(
                2 * l, b1 + l * D, g2 + (l - 1) * D, bb2 + (l - 1) * D,
                2 * (l - 1) + 1, 2 * l);
        k_gemm<2><<<GEMM_GRID, 256, GEMM_SMEM>>>(
            2 * l + 1, b2 + l * D, g1 + l * D, bb1 + l * D, 2 * l, 2 * l + 1);
    }

    k_poolact<<<NG, 256>>>(7, g2 + 3 * D, bb2 + 3 * D, out_h, out_gf);
}

// round 17
// speedup vs baseline: 1.4792x; 1.2559x over previous
#include <cuda_runtime.h>
#include <cstdint>

#define NN 50000
#define NE 500000
#define D 128
#define NL 4
#define NG 64
#define FIXEDDIM 10000
#define BNEPS 1e-5f

// ---------------- scratch (device globals) ----------------------------------
__device__ float g_h[NN * D];
__device__ float g_z1[NN * D];
__device__ float g_z2[NN * D];
__device__ int g_deg[NN];
__device__ int g_rowptr[NN + 1];
__device__ int g_cursor[NN];
__device__ int g_col[NE];
__device__ int g_starts[NG + 1];
__device__ double g_bsum8[8 * D];
__device__ double g_bsq8[8 * D];
__device__ uint4 g_bw4[8 * 4352];   // packed bf16 hi/lo W, [gemm][n][k2][hi,lo], 136 words/row

// ---------------- helpers ----------------------------------------------------
__device__ __forceinline__ void pack_hilo(float v0, float v1, uint32_t& hp, uint32_t& lp) {
    asm("cvt.rn.bf16x2.f32 %0, %1, %2;" : "=r"(hp) : "f"(v1), "f"(v0));
    float h0 = __uint_as_float(hp << 16);
    float h1 = __uint_as_float(hp & 0xffff0000u);
    float r0 = v0 - h0, r1 = v1 - h1;
    asm("cvt.rn.bf16x2.f32 %0, %1, %2;" : "=r"(lp) : "f"(r1), "f"(r0));
}

__device__ __forceinline__ void bn_params(int slot, const float* __restrict__ g,
                                          const float* __restrict__ b, int c,
                                          float& sc, float& sh) {
    double m = g_bsum8[slot * D + c] / (double)NN;
    double var = g_bsq8[slot * D + c] / (double)NN - m * m;
    float s = g[c] * rsqrtf((float)var + BNEPS);
    sc = s;
    sh = b[c] - (float)m * s;
}

#define MMA16(cc, a, b) \
    asm volatile("mma.sync.aligned.m16n8k16.row.col.f32.bf16.bf16.f32 " \
                 "{%0,%1,%2,%3},{%4,%5,%6,%7},{%8,%9},{%0,%1,%2,%3};" \
                 : "+f"((cc)[0]), "+f"((cc)[1]), "+f"((cc)[2]), "+f"((cc)[3]) \
                 : "r"((a)[0]), "r"((a)[1]), "r"((a)[2]), "r"((a)[3]), \
                   "r"((b)[0]), "r"((b)[1]))

__device__ __forceinline__ float4 affrelu(float4 a, float4 s, float4 h) {
    a.x = fmaxf(a.x * s.x + h.x, 0.f);
    a.y = fmaxf(a.y * s.y + h.y, 0.f);
    a.z = fmaxf(a.z * s.z + h.z, 0.f);
    a.w = fmaxf(a.w * s.w + h.w, 0.f);
    return a;
}
__device__ __forceinline__ void acc4(float4& a, float4 t) {
    a.x += t.x; a.y += t.y; a.z += t.z; a.w += t.w;
}

// ---------------- launch #1: zero + prepw ------------------------------------
__global__ void k_setup0(const float* __restrict__ w1, const float* __restrict__ w2) {
    int i = blockIdx.x * 256 + threadIdx.x;  // 0..65535
    if (i < NN) g_deg[i] = 0;
    if (i < 8 * D) { g_bsum8[i] = 0.0; g_bsq8[i] = 0.0; }
    int j = i >> 13, rem = i & 8191;
    int n = rem >> 6, k2 = rem & 63;
    int l = j >> 1;
    const float* W = (j & 1) ? w2 : w1;
    float v0 = W[l * D * D + (2 * k2) * D + n];
    float v1 = W[l * D * D + (2 * k2 + 1) * D + n];
    uint32_t hp, lp;
    pack_hilo(v0, v1, hp, lp);
    uint32_t* bw = (uint32_t*)g_bw4;
    bw[j * 17408 + n * 136 + k2 * 2] = hp;
    bw[j * 17408 + n * 136 + k2 * 2 + 1] = lp;
}

// ---------------- launch #2: degree count (4 edges/thread) --------------------
__global__ void k_deg(const int4* __restrict__ dst4) {
    int e4 = blockIdx.x * blockDim.x + threadIdx.x;
    if (e4 < NE / 4) {
        int4 d = dst4[e4];
        atomicAdd(&g_deg[d.x], 1);
        atomicAdd(&g_deg[d.y], 1);
        atomicAdd(&g_deg[d.z], 1);
        atomicAdd(&g_deg[d.w], 1);
    }
}

// ---------------- launch #3: emit rowptr/cursor -------------------------------
__global__ void k_emit() {
    __shared__ int wsum[32];
    __shared__ int sred[32];
    int tid = threadIdx.x;
    int lane = tid & 31, wid = tid >> 5;
    int base = blockIdx.x * 1024;

    int pre = 0;
    for (int i = tid; i < base; i += 1024) pre += g_deg[i];
#pragma unroll
    for (int off = 16; off > 0; off >>= 1) pre += __shfl_down_sync(0xffffffffu, pre, off);
    if (lane == 0) sred[wid] = pre;
    __syncthreads();
    if (tid < 32) {
        int v = sred[tid];
#pragma unroll
        for (int off = 16; off > 0; off >>= 1) v += __shfl_down_sync(0xffffffffu, v, off);
        if (tid == 0) sred[0] = v;
    }

    int i = base + tid;
    int d = (i < NN) ? g_deg[i] : 0;
    int x = d;
#pragma unroll
    for (int off = 1; off < 32; off <<= 1) {
        int y = __shfl_up_sync(0xffffffffu, x, off);
        if (lane >= off) x += y;
    }
    if (lane == 31) wsum[wid] = x;
    __syncthreads();
    if (tid < 32) {
        int w = wsum[tid];
#pragma unroll
        for (int off = 1; off < 32; off <<= 1) {
            int y = __shfl_up_sync(0xffffffffu, w, off);
            if (tid >= off) w += y;
        }
        wsum[tid] = w;
    }
    __syncthreads();
    int poff = sred[0];
    if (i < NN) {
        int excl = x - d + (wid ? wsum[wid - 1] : 0) + poff;
        g_rowptr[i] = excl;
        g_cursor[i] = excl;
    }
    if (i == 0) g_rowptr[NN] = NE;
}

// ---------------- launch #4: fill + init + bounds -----------------------------
#define FILL_BLKS 1954
#define INIT_BLKS 6250
#define BND_BLKS 196
__global__ void k_setup1(const int* __restrict__ src, const int* __restrict__ dst,
                         const int* __restrict__ feat_id,
                         const float4* __restrict__ w, const float4* __restrict__ b,
                         const float4* __restrict__ demb, const int* __restrict__ batch) {
    int blk = blockIdx.x;
    if (blk < FILL_BLKS) {
        int e = blk * 256 + threadIdx.x;
        if (e < NE) {
            int pos = atomicAdd(&g_cursor[dst[e]], 1);
            g_col[pos] = src[e];
        }
    } else if (blk < FILL_BLKS + INIT_BLKS) {
        int i = (blk - FILL_BLKS) * 256 + threadIdx.x;
        int v = i >> 5, j = i & 31;
        if (v >= NN) return;
        int fid = feat_id[v] % FIXEDDIM;
        int dg = g_deg[v];
        if (dg > 1000) dg = 1000;
        float4 a = w[fid * 32 + j];
        float4 bb = b[j];
        float4 dd = demb[dg * 32 + j];
        float4 r;
        r.x = a.x + bb.x + dd.x;
        r.y = a.y + bb.y + dd.y;
        r.z = a.z + bb.z + dd.z;
        r.w = a.w + bb.w + dd.w;
        ((float4*)g_h)[v * 32 + j] = r;
    } else {
        int i = (blk - FILL_BLKS - INIT_BLKS) * 256 + threadIdx.x;
        if (i >= NN) return;
        if (i == 0) {
            g_starts[batch[0]] = 0;
            g_starts[NG] = NN;
        } else if (batch[i] != batch[i - 1]) {
            g_starts[batch[i]] = i;
        }
    }
}

// ---------------- persistent bf16x3 GEMM, fused staging ----------------------
// MODE 0: A = gather(g_h)            -> out g_z1
// MODE 1: A = gather(affrelu(g_z2))  -> out g_z1
// MODE 2: A = affrelu(g_z1)          -> out g_z2
// smem words: As 8704 | Bs 17408 | ssum/ssq/ssc/ssh 512 | IDX 2048 (8 warps x 256)
#define SMW_BS 8704
#define SMW_SSUM 26112
#define SMW_SSQ 26240
#define SMW_SC 26368
#define SMW_SH 26496
#define SMW_IDX 26624
#define GEMM_SMEM (28672 * 4)
#define NTILES ((NN + 63) / 64)  // 782
#define GEMM_GRID 296

template <int MODE>
__global__ __launch_bounds__(256, 2) void k_gemm(
    int wsel, const float* __restrict__ bias,
    const float* __restrict__ bng, const float* __restrict__ bnb,
    int inSlot, int outSlot) {
    float* __restrict__ out = (MODE == 2) ? g_z2 : g_z1;
    const uint32_t* __restrict__ Bw = (const uint32_t*)g_bw4 + wsel * 17408;

    extern __shared__ uint32_t S[];
    float* ssum = (float*)(S + SMW_SSUM);
    float* ssq = (float*)(S + SMW_SSQ);
    float* ssc = (float*)(S + SMW_SC);
    float* ssh = (float*)(S + SMW_SH);

    int tid = threadIdx.x, lane = tid & 31, wid = tid >> 5;
    int warp_m = wid >> 2, warp_n = wid & 3;
    int g = lane >> 2, tg = lane & 3;

    if (tid < 128) {
        ssum[tid] = 0.f;
        ssq[tid] = 0.f;
        if (MODE != 0) {
            float sc, sh;
            bn_params(inSlot, bng, bnb, tid, sc, sh);
            ssc[tid] = sc;
            ssh[tid] = sh;
        }
    }
    // B: load once per block
    {
        const uint4* srcp = (const uint4*)Bw;
        uint4* dst = (uint4*)(S + SMW_BS);
#pragma unroll
        for (int i = 0; i < 17; i++) dst[tid + i * 256] = srcp[tid + i * 256];
    }
    __syncthreads();

    float bb0[4], bb1[4];
#pragma unroll
    for (int u = 0; u < 4; u++) {
        int col = warp_n * 32 + u * 8 + tg * 2;
        bb0[u] = __ldg(&bias[col]);
        bb1[u] = __ldg(&bias[col + 1]);
    }
    float4 sc4, sh4;
    if (MODE == 1) {
        sc4 = ((float4*)ssc)[lane];
        sh4 = ((float4*)ssh)[lane];
    }

    float sl[8], ql[8];
#pragma unroll
    for (int j = 0; j < 8; j++) { sl[j] = 0.f; ql[j] = 0.f; }

    for (int tile = blockIdx.x; tile < NTILES; tile += GEMM_GRID) {
        int rowBase = tile * 64;

        if (MODE == 2) {
            // two-phase dense staging with float4 (8 LDG.128, MLP=8x16B/thread)
            float4 vb[8];
#pragma unroll
            for (int it = 0; it < 8; it++) {
                int i = it * 256 + tid;
                int row = i >> 5, kp4 = i & 31;
                int grow = rowBase + row;
                vb[it] = (grow < NN) ? *(const float4*)&g_z1[grow * D + kp4 * 4]
                                     : make_float4(0.f, 0.f, 0.f, 0.f);
            }
#pragma unroll
            for (int it = 0; it < 8; it++) {
                int i = it * 256 + tid;
                int row = i >> 5, kp4 = i & 31;
                float4 v = vb[it];
                v.x = fmaxf(v.x * ssc[kp4 * 4] + ssh[kp4 * 4], 0.f);
                v.y = fmaxf(v.y * ssc[kp4 * 4 + 1] + ssh[kp4 * 4 + 1], 0.f);
                v.z = fmaxf(v.z * ssc[kp4 * 4 + 2] + ssh[kp4 * 4 + 2], 0.f);
                v.w = fmaxf(v.w * ssc[kp4 * 4 + 3] + ssh[kp4 * 4 + 3], 0.f);
                uint32_t h0, l0, h1, l1;
                pack_hilo(v.x, v.y, h0, l0);
                pack_hilo(v.z, v.w, h1, l1);
                *(uint4*)(S + row * 136 + kp4 * 4) = make_uint4(h0, l0, h1, l1);
            }
        } else {
            const float4* __restrict__ h4 = (MODE == 0) ? (const float4*)g_h
                                                        : (const float4*)g_z2;
            int* IDX = (int*)(S + SMW_IDX) + wid * 256;
            int v0 = rowBase + wid * 8;
            int rpi = v0 + (lane < 8 ? lane : 8);
            if (rpi > NN) rpi = NN;
            int rpl = g_rowptr[rpi];
            int base = __shfl_sync(0xffffffffu, rpl, 0);
            int cnt = __shfl_sync(0xffffffffu, rpl, 8) - base;
#pragma unroll
            for (int k = 0; k < 8; k++) {
                int p = k * 32 + lane;
                if (p < cnt) IDX[p] = g_col[base + p];
            }
            __syncwarp();
#pragma unroll
            for (int rr = 0; rr < 8; rr++) {
                int row = wid * 8 + rr;
                int v = rowBase + row;
                float4 a0 = make_float4(0.f, 0.f, 0.f, 0.f);
                float4 a1 = a0, a2 = a0, a3 = a0;
                if (v < NN) {
                    a0 = h4[v * 32 + lane];
                    if (MODE == 1) a0 = affrelu(a0, sc4, sh4);
                    int beg = __shfl_sync(0xffffffffu, rpl, rr) - base;
                    int end = __shfl_sync(0xffffffffu, rpl, rr + 1) - base;
                    int j = beg;
                    for (; j + 7 < end; j += 8) {
                        int s0, s1, s2, s3, s4, s5, s6, s7;
                        if (j + 7 < 256) {
                            s0 = IDX[j];     s1 = IDX[j + 1];
                            s2 = IDX[j + 2]; s3 = IDX[j + 3];
                            s4 = IDX[j + 4]; s5 = IDX[j + 5];
                            s6 = IDX[j + 6]; s7 = IDX[j + 7];
                        } else {
                            s0 = g_col[base + j];     s1 = g_col[base + j + 1];
                            s2 = g_col[base + j + 2]; s3 = g_col[base + j + 3];
                            s4 = g_col[base + j + 4]; s5 = g_col[base + j + 5];
                            s6 = g_col[base + j + 6]; s7 = g_col[base + j + 7];
                        }
                        float4 t0 = h4[s0 * 32 + lane];
                        float4 t1 = h4[s1 * 32 + lane];
                        float4 t2 = h4[s2 * 32 + lane];
                        float4 t3 = h4[s3 * 32 + lane];
                        float4 t4 = h4[s4 * 32 + lane];
                        float4 t5 = h4[s5 * 32 + lane];
                        float4 t6 = h4[s6 * 32 + lane];
                        float4 t7 = h4[s7 * 32 + lane];
                        if (MODE == 1) {
                            t0 = affrelu(t0, sc4, sh4); t1 = affrelu(t1, sc4, sh4);
                            t2 = affrelu(t2, sc4, sh4); t3 = affrelu(t3, sc4, sh4);
                            t4 = affrelu(t4, sc4, sh4); t5 = affrelu(t5, sc4, sh4);
                            t6 = affrelu(t6, sc4, sh4); t7 = affrelu(t7, sc4, sh4);
                        }
                        acc4(a0, t0); acc4(a1, t1); acc4(a2, t2); acc4(a3, t3);
                        acc4(a0, t4); acc4(a1, t5); acc4(a2, t6); acc4(a3, t7);
                    }
                    for (; j + 1 < end; j += 2) {
                        int s0 = (j + 1 < 256) ? IDX[j] : g_col[base + j];
                        int s1 = (j + 1 < 256) ? IDX[j + 1] : g_col[base + j + 1];
                        float4 t0 = h4[s0 * 32 + lane];
                        float4 t1 = h4[s1 * 32 + lane];
                        if (MODE == 1) {
                            t0 = affrelu(t0, sc4, sh4); t1 = affrelu(t1, sc4, sh4);
                        }
                        acc4(a0, t0); acc4(a1, t1);
                    }
                    if (j < end) {
                        int s = (j < 256) ? IDX[j] : g_col[base + j];
                        float4 t = h4[s * 32 + lane];
                        if (MODE == 1) t = affrelu(t, sc4, sh4);
                        acc4(a0, t);
                    }
                    acc4(a0, a1); acc4(a2, a3); acc4(a0, a2);
                }
                uint32_t h0, l0, h1, l1;
                pack_hilo(a0.x, a0.y, h0, l0);
                pack_hilo(a0.z, a0.w, h1, l1);
                *(uint4*)(S + row * 136 + lane * 4) = make_uint4(h0, l0, h1, l1);
            }
        }
        __syncthreads();

        float c[2][4][4];
#pragma unroll
        for (int t = 0; t < 2; t++)
#pragma unroll
            for (int u = 0; u < 4; u++)
#pragma unroll
                for (int j = 0; j < 4; j++) c[t][u][j] = 0.f;

#pragma unroll
        for (int ks = 0; ks < 8; ks++) {
            int kw = (ks * 8 + tg) * 2;
            uint32_t ah[2][4], al[2][4];
#pragma unroll
            for (int t = 0; t < 2; t++) {
                int r0 = warp_m * 32 + t * 16 + g;
                uint2 p0 = *(uint2*)(S + r0 * 136 + kw);
                uint2 p1 = *(uint2*)(S + (r0 + 8) * 136 + kw);
                uint2 p2 = *(uint2*)(S + r0 * 136 + kw + 8);
                uint2 p3 = *(uint2*)(S + (r0 + 8) * 136 + kw + 8);
                ah[t][0] = p0.x; al[t][0] = p0.y;
                ah[t][1] = p1.x; al[t][1] = p1.y;
                ah[t][2] = p2.x; al[t][2] = p2.y;
                ah[t][3] = p3.x; al[t][3] = p3.y;
            }
#pragma unroll
            for (int u = 0; u < 4; u++) {
                int n = warp_n * 32 + u * 8 + g;
                uint2 q0 = *(uint2*)(S + SMW_BS + n * 136 + kw);
                uint2 q1 = *(uint2*)(S + SMW_BS + n * 136 + kw + 8);
                uint32_t bh[2] = {q0.x, q1.x};
                uint32_t bl[2] = {q0.y, q1.y};
                MMA16(c[0][u], ah[0], bh);
                MMA16(c[1][u], ah[1], bh);
                MMA16(c[0][u], al[0], bh);
                MMA16(c[1][u], al[1], bh);
                MMA16(c[0][u], ah[0], bl);
                MMA16(c[1][u], ah[1], bl);
            }
        }

#pragma unroll
        for (int u = 0; u < 4; u++) {
            int col = warp_n * 32 + u * 8 + tg * 2;
#pragma unroll
            for (int t = 0; t < 2; t++) {
                int row0 = rowBase + warp_m * 32 + t * 16 + g;
                float v0 = c[t][u][0] + bb0[u], v1 = c[t][u][1] + bb1[u];
                if (row0 < NN) {
                    *(float2*)&out[row0 * D + col] = make_float2(v0, v1);
                    sl[u * 2] += v0; ql[u * 2] += v0 * v0;
                    sl[u * 2 + 1] += v1; ql[u * 2 + 1] += v1 * v1;
                }
                int row1 = row0 + 8;
                float v2 = c[t][u][2] + bb0[u], v3 = c[t][u][3] + bb1[u];
                if (row1 < NN) {
                    *(float2*)&out[row1 * D + col] = make_float2(v2, v3);
                    sl[u * 2] += v2; ql[u * 2] += v2 * v2;
                    sl[u * 2 + 1] += v3; ql[u * 2 + 1] += v3 * v3;
                }
            }
        }
        __syncthreads();
    }

    // one-time BN stat reduction
#pragma unroll
    for (int j = 0; j < 8; j++) {
#pragma unroll
        for (int off = 4; off < 32; off <<= 1) {
            sl[j] += __shfl_xor_sync(0xffffffffu, sl[j], off);
            ql[j] += __shfl_xor_sync(0xffffffffu, ql[j], off);
        }
    }
    if (g == 0) {
#pragma unroll
        for (int u = 0; u < 4; u++) {
            int col = warp_n * 32 + u * 8 + tg * 2;
            atomicAdd(&ssum[col], sl[u * 2]);
            atomicAdd(&ssq[col], ql[u * 2]);
            atomicAdd(&ssum[col + 1], sl[u * 2 + 1]);
            atomicAdd(&ssq[col + 1], ql[u * 2 + 1]);
        }
    }
    __syncthreads();
    if (tid < 128) {
        atomicAdd(&g_bsum8[outSlot * D + tid], (double)ssum[tid]);
        atomicAdd(&g_bsq8[outSlot * D + tid], (double)ssq[tid]);
    }
}

// ---------------- pooling: 1024 threads, 8-way row-parallel ------------------
__global__ __launch_bounds__(1024) void k_poolact(
    int slot, const float* __restrict__ bng, const float* __restrict__ bnb,
    float* __restrict__ out_h, float* __restrict__ out_gf) {
    __shared__ float ssc[128], ssh[128], sh[1024];
    if (threadIdx.x < 128) {
        float sc, s2;
        bn_params(slot, bng, bnb, threadIdx.x, sc, s2);
        ssc[threadIdx.x] = sc;
        ssh[threadIdx.x] = s2;
    }
    __syncthreads();
    int g = blockIdx.x;
    int s = g_starts[g], e = g_starts[g + 1];
    int col = threadIdx.x & 127, part = threadIdx.x >> 7;  // 8 row-partitions
    float sc = ssc[col], sf = ssh[col];
    float acc0 = 0.f, acc1 = 0.f;
    int r = s + part;
    for (; r + 8 < e; r += 16) {
        float x0 = g_z2[r * D + col];
        float x1 = g_z2[(r + 8) * D + col];
        float v0 = fmaxf(x0 * sc + sf, 0.f);
        float v1 = fmaxf(x1 * sc + sf, 0.f);
        out_h[r * D + col] = v0;
        out_h[(r + 8) * D + col] = v1;
        acc0 += v0;
        acc1 += v1;
    }
    if (r < e) {
        float v0 = fmaxf(g_z2[r * D + col] * sc + sf, 0.f);
        out_h[r * D + col] = v0;
        acc0 += v0;
    }
    sh[threadIdx.x] = acc0 + acc1;
    __syncthreads();
    if (part == 0) {
        float tot = 0.f;
#pragma unroll
        for (int p = 0; p < 8; p++) tot += sh[p * 128 + col];
        int cnt = e - s;
        if (cnt < 1) cnt = 1;
        out_gf[g * D + col] = tot / (float)cnt;
    }
}

// ---------------- launch -----------------------------------------------------
extern "C" void kernel_launch(void* const* d_in, const int* in_sizes, int n_in,
                              void* d_out, int out_size) {
    const int* feat_id = (const int*)d_in[0];
    const int* ei      = (const int*)d_in[1];
    const int* batch   = (const int*)d_in[2];
    const float* vpw   = (const float*)d_in[3];
    const float* vpb   = (const float*)d_in[4];
    const float* demb  = (const float*)d_in[5];
    const float* w1    = (const float*)d_in[6];
    const float* b1    = (const float*)d_in[7];
    const float* g1    = (const float*)d_in[8];
    const float* bb1   = (const float*)d_in[9];
    const float* w2    = (const float*)d_in[10];
    const float* b2    = (const float*)d_in[11];
    const float* g2    = (const float*)d_in[12];
    const float* bb2   = (const float*)d_in[13];

    float* out    = (float*)d_out;
    float* out_gf = out;
    float* out_h  = out + NG * D;

    const int* src = ei;
    const int* dst = ei + NE;

    cudaFuncSetAttribute(k_gemm<0>, cudaFuncAttributeMaxDynamicSharedMemorySize, GEMM_SMEM);
    cudaFuncSetAttribute(k_gemm<1>, cudaFuncAttributeMaxDynamicSharedMemorySize, GEMM_SMEM);
    cudaFuncSetAttribute(k_gemm<2>, cudaFuncAttributeMaxDynamicSharedMemorySize, GEMM_SMEM);

    k_setup0<<<256, 256>>>(w1, w2);
    k_deg<<<(NE / 4 + 255) / 256, 256>>>((const int4*)dst);
    k_emit<<<49, 1024>>>();
    k_setup1<<<FILL_BLKS + INIT_BLKS + BND_BLKS, 256>>>(
        src, dst, feat_id, (const float4*)vpw, (const float4*)vpb,
        (const float4*)demb, batch);

    for (int l = 0; l < NL; l++) {
        if (l == 0)
            k_gemm<0><<<GEMM_GRID, 256, GEMM_SMEM>>>(
                0, b1, (const float*)0, (const float*)0, -1, 0);
        else
            k_gemm<1><<<GEMM_GRID, 256, GEMM_SMEM>>>(
                2 * l, b1 + l * D, g2 + (l - 1) * D, bb2 + (l - 1) * D,
                2 * (l - 1) + 1, 2 * l);
        k_gemm<2><<<GEMM_GRID, 256, GEMM_SMEM>>>(
            2 * l + 1, b2 + l * D, g1 + l * D, bb1 + l * D, 2 * l, 2 * l + 1);
    }

    k_poolact<<<NG, 1024>>>(7, g2 + 3 * D, bb2 + 3 * D, out_h, out_gf);
}